// round 7
// baseline (speedup 1.0000x reference)
#include <cuda_runtime.h>
#include <cstdint>

// ---------------------------------------------------------------------------
// 4-layer LSTM (B=128, T=1024, D=128, H=[100,100,200,200]) + dense head.
// R6: precompute GEMMs moved to tensor cores (mma.sync m16n8k8 tf32, 3-term
// hi/lo split for fp32-grade accuracy). Scans identical to R5.
// ---------------------------------------------------------------------------

#define TLEN 1024
#define BSZ  128
#define HPAD 256

typedef unsigned long long u64;

__device__ float g_zx[(size_t)BSZ * TLEN * 800];  // x@Wx+b, layout [b][t][j][4]
__device__ float g_seq[(size_t)BSZ * TLEN * 200]; // layer output sequence
__device__ float g_hbuf[BSZ * HPAD];              // final h for dense head

#define FMA2(d, a, b, c) \
    asm("fma.rn.f32x2 %0, %1, %2, %3;" : "=l"(d) : "l"(a), "l"(b), "l"(c))

__device__ __forceinline__ u64 pack2(float lo, float hi) {
    u64 d;
    asm("mov.b64 %0, {%1, %2};" : "=l"(d)
        : "r"(__float_as_uint(lo)), "r"(__float_as_uint(hi)));
    return d;
}
__device__ __forceinline__ float2 unpack2(u64 v) {
    unsigned lo, hi;
    asm("mov.b64 {%0, %1}, %2;" : "=r"(lo), "=r"(hi) : "l"(v));
    return make_float2(__uint_as_float(lo), __uint_as_float(hi));
}

__device__ __forceinline__ float sigm(float x) {
    return __fdividef(1.0f, 1.0f + __expf(-x));
}
__device__ __forceinline__ float tanh_fast(float x) {
    return 1.0f - __fdividef(2.0f, __expf(2.0f * x) + 1.0f);
}

// ---------------------------------------------------------------------------
// Tensor-core precompute GEMM (tf32 3-term split == fp32-grade accuracy).
// C[M=BSZ*TLEN, n] = A[M,K] @ W[K, colmap(n)] + bias[colmap(n)], into g_zx.
// colmap(n) = (n&3)*Hn + (n>>2)  (gate-interleaved zx layout for the scans).
// CTA tile 64x64, 128 threads, 4 warps of 32x32; per k8: hi/lo planes staged
// in SMEM with k-pair permutation so each mma fragment is one LDS.64.
// ---------------------------------------------------------------------------
__device__ __forceinline__ unsigned tf32cvt(float x) {
    unsigned r; asm("cvt.rna.tf32.f32 %0, %1;" : "=r"(r) : "f"(x)); return r;
}
__device__ __forceinline__ void mma_tf32(float* c, const unsigned* a, const unsigned* b) {
    asm volatile(
        "mma.sync.aligned.m16n8k8.row.col.f32.tf32.tf32.f32 "
        "{%0,%1,%2,%3}, {%4,%5,%6,%7}, {%8,%9}, {%0,%1,%2,%3};"
        : "+f"(c[0]), "+f"(c[1]), "+f"(c[2]), "+f"(c[3])
        : "r"(a[0]), "r"(a[1]), "r"(a[2]), "r"(a[3]), "r"(b[0]), "r"(b[1]));
}

template <int K>
__global__ void __launch_bounds__(128)
gemm_tf32(const float* __restrict__ Ain, const float* __restrict__ W,
          const float* __restrict__ bias, int N, int Hn, int use_seq)
{
    constexpr int NCH = (K + 7) / 8;

    __shared__ __align__(16) float Ahi[64][8], Alo[64][8];
    __shared__ __align__(16) float Bhi[64][8], Blo[64][8];

    const float* __restrict__ A = use_seq ? g_seq : Ain;
    const int tid  = threadIdx.x;
    const int m0   = blockIdx.y * 64, n0 = blockIdx.x * 64;
    const int warp = tid >> 5, lane = tid & 31;
    const int g    = lane >> 2, tig = lane & 3;
    const int wm   = (warp >> 1) * 32, wn = (warp & 1) * 32;

    const int sa_row = tid >> 1, sa_half = tid & 1;     // A stage: 64 rows x 2 halves
    const int sb_k   = tid >> 4, sb_n4 = (tid & 15) * 4; // B stage: 8 k x 16 col-quads

    float acc[2][4][4];
    #pragma unroll
    for (int mt = 0; mt < 2; ++mt)
        #pragma unroll
        for (int nt = 0; nt < 4; ++nt)
            #pragma unroll
            for (int i = 0; i < 4; ++i) acc[mt][nt][i] = 0.0f;

    for (int c = 0; c < NCH; ++c) {
        const int k0 = c * 8;

        // ---- stage A (64 x 8) split hi/lo, k-pair permuted ----
        {
            float av[4];
            const int kb = k0 + sa_half * 4;
            if (kb + 4 <= K) {
                float4 v = *reinterpret_cast<const float4*>(
                    &A[(size_t)(m0 + sa_row) * K + kb]);
                av[0] = v.x; av[1] = v.y; av[2] = v.z; av[3] = v.w;
            } else {
                #pragma unroll
                for (int e = 0; e < 4; ++e)
                    av[e] = (kb + e < K) ? A[(size_t)(m0 + sa_row) * K + kb + e] : 0.0f;
            }
            #pragma unroll
            for (int e = 0; e < 4; ++e) {
                int k = sa_half * 4 + e;
                int p = (k & 3) * 2 + (k >> 2);   // pairs (k, k+4) adjacent
                unsigned hb = tf32cvt(av[e]);
                float lo = av[e] - __uint_as_float(hb);
                Ahi[sa_row][p] = __uint_as_float(hb);
                Alo[sa_row][p] = __uint_as_float(tf32cvt(lo));
            }
        }
        // ---- stage B (8 x 64) with column permutation, split hi/lo ----
        {
            const int p = (sb_k & 3) * 2 + (sb_k >> 2);
            #pragma unroll
            for (int i = 0; i < 4; ++i) {
                int n = sb_n4 + i, nglob = n0 + n;
                float v = 0.0f;
                if ((k0 + sb_k < K) && (nglob < N))
                    v = W[(size_t)(k0 + sb_k) * N + (nglob & 3) * Hn + (nglob >> 2)];
                unsigned hb = tf32cvt(v);
                float lo = v - __uint_as_float(hb);
                Bhi[n][p] = __uint_as_float(hb);
                Blo[n][p] = __uint_as_float(tf32cvt(lo));
            }
        }
        __syncthreads();

        // ---- fragments (one LDS.64 each) ----
        unsigned ahi[2][4], alo[2][4], bhi[4][2], blo[4][2];
        #pragma unroll
        for (int mt = 0; mt < 2; ++mt) {
            int row = wm + mt * 16 + g;
            float2 t;
            t = *reinterpret_cast<const float2*>(&Ahi[row][2 * tig]);
            ahi[mt][0] = __float_as_uint(t.x); ahi[mt][2] = __float_as_uint(t.y);
            t = *reinterpret_cast<const float2*>(&Ahi[row + 8][2 * tig]);
            ahi[mt][1] = __float_as_uint(t.x); ahi[mt][3] = __float_as_uint(t.y);
            t = *reinterpret_cast<const float2*>(&Alo[row][2 * tig]);
            alo[mt][0] = __float_as_uint(t.x); alo[mt][2] = __float_as_uint(t.y);
            t = *reinterpret_cast<const float2*>(&Alo[row + 8][2 * tig]);
            alo[mt][1] = __float_as_uint(t.x); alo[mt][3] = __float_as_uint(t.y);
        }
        #pragma unroll
        for (int nt = 0; nt < 4; ++nt) {
            int coln = wn + nt * 8 + g;
            float2 t;
            t = *reinterpret_cast<const float2*>(&Bhi[coln][2 * tig]);
            bhi[nt][0] = __float_as_uint(t.x); bhi[nt][1] = __float_as_uint(t.y);
            t = *reinterpret_cast<const float2*>(&Blo[coln][2 * tig]);
            blo[nt][0] = __float_as_uint(t.x); blo[nt][1] = __float_as_uint(t.y);
        }
        // ---- 3-term tf32 mma: hh + lh + hl ----
        #pragma unroll
        for (int mt = 0; mt < 2; ++mt)
            #pragma unroll
            for (int nt = 0; nt < 4; ++nt) {
                mma_tf32(acc[mt][nt], ahi[mt], bhi[nt]);
                mma_tf32(acc[mt][nt], alo[mt], bhi[nt]);
                mma_tf32(acc[mt][nt], ahi[mt], blo[nt]);
            }
        __syncthreads();
    }

    // ---- epilogue: bias (permuted) + store ----
    #pragma unroll
    for (int nt = 0; nt < 4; ++nt) {
        int col = n0 + wn + nt * 8 + tig * 2;
        if (col >= N) continue;
        float b0 = bias[(col & 3) * Hn + (col >> 2)];
        float b1 = bias[((col + 1) & 3) * Hn + ((col + 1) >> 2)];
        #pragma unroll
        for (int mt = 0; mt < 2; ++mt) {
            int row = m0 + wm + mt * 16 + g;
            float2 v0 = make_float2(acc[mt][nt][0] + b0, acc[mt][nt][1] + b1);
            float2 v1 = make_float2(acc[mt][nt][2] + b0, acc[mt][nt][3] + b1);
            *reinterpret_cast<float2*>(&g_zx[(size_t)row * N + col])       = v0;
            *reinterpret_cast<float2*>(&g_zx[(size_t)(row + 8) * N + col]) = v1;
        }
    }
}

// ---------------------------------------------------------------------------
// H=100 scan: 1 CTA per batch row. Wh in regs (k-paired f32x2), h in SMEM.
// zx: one float4 per thread per step, 2-deep register prefetch ring.
// ---------------------------------------------------------------------------
__global__ void __launch_bounds__(512, 1)
scan100(const float* __restrict__ Wh)
{
    __shared__ __align__(16) float  h_s[104];
    __shared__ __align__(16) float4 zp[5][100];

    const int tid = threadIdx.x;
    const int b   = blockIdx.x;
    const int s   = tid / 100;
    const int j   = tid % 100;
    const bool ga  = (tid < 500);
    const bool red = (tid < 100);

    u64 w2[10][4];
    if (ga) {
        const int k0 = s * 20;
        #pragma unroll
        for (int kp = 0; kp < 10; ++kp)
            #pragma unroll
            for (int g = 0; g < 4; ++g)
                w2[kp][g] = pack2(Wh[(k0 + 2 * kp)     * 400 + g * 100 + j],
                                  Wh[(k0 + 2 * kp + 1) * 400 + g * 100 + j]);
    }
    if (red) h_s[j] = 0.0f;
    float c = 0.0f;
    __syncthreads();

    const float* __restrict__ zbase = g_zx + (size_t)b * TLEN * 400;
    float* __restrict__ ybase = g_seq + (size_t)b * TLEN * 100;

    float4 zb0 = make_float4(0, 0, 0, 0), zb1 = zb0;
    if (red) {
        zb0 = *reinterpret_cast<const float4*>(zbase + j * 4);
        zb1 = *reinterpret_cast<const float4*>(zbase + 400 + j * 4);
    }

    auto step = [&](int t, float4& zslot) {
        float4 zc;
        if (red) {
            zc = zslot;
            int tp = (t + 2 < TLEN) ? t + 2 : t;
            zslot = *reinterpret_cast<const float4*>(zbase + (size_t)tp * 400 + j * 4);
        }
        if (ga) {
            u64 a0 = 0ull, a1 = 0ull, a2 = 0ull, a3 = 0ull;
            const ulonglong2* hp = reinterpret_cast<const ulonglong2*>(h_s);
            const int qb = s * 5;
            #pragma unroll
            for (int q = 0; q < 5; ++q) {
                ulonglong2 hv = hp[qb + q];
                FMA2(a0, hv.x, w2[2 * q][0], a0);
                FMA2(a1, hv.x, w2[2 * q][1], a1);
                FMA2(a2, hv.x, w2[2 * q][2], a2);
                FMA2(a3, hv.x, w2[2 * q][3], a3);
                FMA2(a0, hv.y, w2[2 * q + 1][0], a0);
                FMA2(a1, hv.y, w2[2 * q + 1][1], a1);
                FMA2(a2, hv.y, w2[2 * q + 1][2], a2);
                FMA2(a3, hv.y, w2[2 * q + 1][3], a3);
            }
            float2 p0 = unpack2(a0), p1 = unpack2(a1), p2 = unpack2(a2), p3 = unpack2(a3);
            zp[s][j] = make_float4(p0.x + p0.y, p1.x + p1.y, p2.x + p2.y, p3.x + p3.y);
        }
        __syncthreads();
        if (red) {
            float z0 = zc.x, z1 = zc.y, z2 = zc.z, z3 = zc.w;
            #pragma unroll
            for (int ss = 0; ss < 5; ++ss) {
                float4 p = zp[ss][j];
                z0 += p.x; z1 += p.y; z2 += p.z; z3 += p.w;
            }
            float gi = sigm(z0), gf = sigm(z1), gg = tanh_fast(z2), go = sigm(z3);
            c = gf * c + gi * gg;
            float h = go * tanh_fast(c);
            h_s[j] = h;
            ybase[(size_t)t * 100 + j] = h;
        }
        __syncthreads();
    };

    for (int t = 0; t < TLEN; t += 2) {
        step(t,     zb0);
        step(t + 1, zb1);
    }
}

// ---------------------------------------------------------------------------
// H=200 scan: cluster of 4 CTAs; rank owns j-slice [50r, 50r+50); cluster owns
// 4 batch rows. Wh slice in regs (k-paired f32x2); h double-buffered in SMEM,
// exchanged via DSMEM; zx via float4 + 2-deep prefetch.
// ---------------------------------------------------------------------------
template <int WRITE_Y>
__global__ void __launch_bounds__(512, 1) __cluster_dims__(4, 1, 1)
scan200(const float* __restrict__ Wh)
{
    __shared__ __align__(16) float  h_s[2][4][208];   // [buf][row][k]
    __shared__ __align__(16) float4 zp[10][4][50];    // [split][row][jl]

    const int tid = threadIdx.x;
    uint32_t rank;
    asm("mov.u32 %0, %%cluster_ctarank;" : "=r"(rank));
    const int cl = blockIdx.x >> 2;

    const int s  = tid / 50;               // gemm split 0..9 (tid<500)
    const int jl = tid % 50;
    const bool ga  = (tid < 500);
    const bool red = (tid < 200);          // reduce row = s (0..3)
    const int  rr  = s;
    const int  jg  = (int)rank * 50 + jl;

    uint32_t hs_addr;
    {
        const void* p = (const void*)&h_s[0][0][0];
        asm("{ .reg .u64 t; cvta.to.shared.u64 t, %1; cvt.u32.u64 %0, t; }"
            : "=r"(hs_addr) : "l"(p));
    }

    // k-paired weights: w2[kp][g] = {W[k][g][jg], W[k+1][g][jg]}
    u64 w2[10][4];
    if (ga) {
        const int k0 = s * 20;
        #pragma unroll
        for (int kp = 0; kp < 10; ++kp)
            #pragma unroll
            for (int g = 0; g < 4; ++g)
                w2[kp][g] = pack2(Wh[(k0 + 2 * kp)     * 800 + g * 200 + jg],
                                  Wh[(k0 + 2 * kp + 1) * 800 + g * 200 + jg]);
    }
    for (int i = tid; i < 2 * 4 * 208; i += 512) (&h_s[0][0][0])[i] = 0.0f;
    float c = 0.0f;
    __syncthreads();
    asm volatile("barrier.cluster.arrive.aligned;" ::: "memory");
    asm volatile("barrier.cluster.wait.aligned;" ::: "memory");

    const int b = cl * 4 + rr;
    const float* __restrict__ zbase = g_zx + (size_t)b * TLEN * 800;
    float* __restrict__ ybase = g_seq + (size_t)b * TLEN * 200;

    float4 zb0 = make_float4(0, 0, 0, 0), zb1 = zb0;
    if (red) {
        zb0 = *reinterpret_cast<const float4*>(zbase + jg * 4);
        zb1 = *reinterpret_cast<const float4*>(zbase + 800 + jg * 4);
    }

    auto step = [&](int t, float4& zslot, int cur) {
        float4 zc;
        if (red) {
            zc = zslot;
            int tp = (t + 2 < TLEN) ? t + 2 : t;
            zslot = *reinterpret_cast<const float4*>(zbase + (size_t)tp * 800 + jg * 4);
        }
        if (ga) {
            const int qb = s * 5;
            #pragma unroll
            for (int r2 = 0; r2 < 4; ++r2) {   // one row at a time (reg-lean)
                u64 a0 = 0ull, a1 = 0ull, a2 = 0ull, a3 = 0ull;
                const ulonglong2* hp =
                    reinterpret_cast<const ulonglong2*>(&h_s[cur][r2][0]);
                #pragma unroll
                for (int q = 0; q < 5; ++q) {
                    ulonglong2 hv = hp[qb + q];
                    FMA2(a0, hv.x, w2[2 * q][0], a0);
                    FMA2(a1, hv.x, w2[2 * q][1], a1);
                    FMA2(a2, hv.x, w2[2 * q][2], a2);
                    FMA2(a3, hv.x, w2[2 * q][3], a3);
                    FMA2(a0, hv.y, w2[2 * q + 1][0], a0);
                    FMA2(a1, hv.y, w2[2 * q + 1][1], a1);
                    FMA2(a2, hv.y, w2[2 * q + 1][2], a2);
                    FMA2(a3, hv.y, w2[2 * q + 1][3], a3);
                }
                float2 p0 = unpack2(a0), p1 = unpack2(a1),
                       p2 = unpack2(a2), p3 = unpack2(a3);
                zp[s][r2][jl] = make_float4(p0.x + p0.y, p1.x + p1.y,
                                            p2.x + p2.y, p3.x + p3.y);
            }
        }
        __syncthreads();
        if (red) {
            float z0 = zc.x, z1 = zc.y, z2 = zc.z, z3 = zc.w;
            #pragma unroll
            for (int ss = 0; ss < 10; ++ss) {
                float4 p = zp[ss][rr][jl];
                z0 += p.x; z1 += p.y; z2 += p.z; z3 += p.w;
            }
            float gi = sigm(z0), gf = sigm(z1), gg = tanh_fast(z2), go = sigm(z3);
            c = gf * c + gi * gg;
            float h = go * tanh_fast(c);

            const int nxt = cur ^ 1;
            uint32_t laddr = hs_addr + (uint32_t)((nxt * 4 + rr) * 208 + jg) * 4u;
            #pragma unroll
            for (int p = 0; p < 4; ++p) {
                uint32_t raddr;
                asm("mapa.shared::cluster.u32 %0, %1, %2;"
                    : "=r"(raddr) : "r"(laddr), "r"(p));
                asm volatile("st.shared::cluster.f32 [%0], %1;"
                             :: "r"(raddr), "f"(h) : "memory");
            }
            if (WRITE_Y) ybase[(size_t)t * 200 + jg] = h;
            if (t == TLEN - 1) g_hbuf[b * HPAD + jg] = h;
        }
        asm volatile("barrier.cluster.arrive.aligned;" ::: "memory");
        asm volatile("barrier.cluster.wait.aligned;" ::: "memory");
    };

    for (int t = 0; t < TLEN; t += 2) {
        step(t,     zb0, 0);
        step(t + 1, zb1, 1);
    }
}

// Final dense: out[b, o] = h_last[b, :200] @ Wd + bd.
__global__ void dense_kernel(const float* __restrict__ Wd,
                             const float* __restrict__ bd,
                             float* __restrict__ out)
{
    int idx = blockIdx.x * blockDim.x + threadIdx.x;
    if (idx >= BSZ * 6) return;
    int b = idx / 6, o = idx - b * 6;
    const float* h = g_hbuf + b * HPAD;
    float s = bd[o];
    #pragma unroll 8
    for (int k = 0; k < 200; ++k) s += h[k] * Wd[k * 6 + o];
    out[idx] = s;
}

extern "C" void kernel_launch(void* const* d_in, const int* in_sizes, int n_in,
                              void* d_out, int out_size)
{
    const float* xs  = (const float*)d_in[0];
    const float* Wx0 = (const float*)d_in[1];
    const float* Wh0 = (const float*)d_in[2];
    const float* b0  = (const float*)d_in[3];
    const float* Wx1 = (const float*)d_in[4];
    const float* Wh1 = (const float*)d_in[5];
    const float* b1  = (const float*)d_in[6];
    const float* Wx2 = (const float*)d_in[7];
    const float* Wh2 = (const float*)d_in[8];
    const float* b2  = (const float*)d_in[9];
    const float* Wx3 = (const float*)d_in[10];
    const float* Wh3 = (const float*)d_in[11];
    const float* b3  = (const float*)d_in[12];
    const float* Wd  = (const float*)d_in[13];
    const float* bd  = (const float*)d_in[14];

    const dim3 gN400(7, 2048);    // ceil(400/64) x (131072/64)
    const dim3 gN800(13, 2048);   // ceil(800/64)

    // L0
    gemm_tf32<128><<<gN400, 128>>>(xs, Wx0, b0, 400, 100, 0);
    scan100<<<BSZ, 512>>>(Wh0);
    // L1
    gemm_tf32<100><<<gN400, 128>>>(nullptr, Wx1, b1, 400, 100, 1);
    scan100<<<BSZ, 512>>>(Wh1);
    // L2
    gemm_tf32<100><<<gN800, 128>>>(nullptr, Wx2, b2, 800, 200, 1);
    scan200<1><<<BSZ, 512>>>(Wh2);
    // L3
    gemm_tf32<200><<<gN800, 128>>>(nullptr, Wx3, b3, 800, 200, 1);
    scan200<0><<<BSZ, 512>>>(Wh3);
    // head
    dense_kernel<<<3, 256>>>(Wd, bd, (float*)d_out);
}

// round 8
// speedup vs baseline: 1.3392x; 1.3392x over previous
#include <cuda_runtime.h>
#include <cstdint>

// ---------------------------------------------------------------------------
// 4-layer LSTM (B=128, T=1024, D=128, H=[100,100,200,200]) + dense head.
// R7: GEMMs reverted to the R5 fp32/FFMA2 version (R6 tf32 mma regressed).
// scan200 per-step cluster barrier replaced by st.async + mbarrier tx-count
// (saves ~400 cyc/step of UCGABAR_WAIT). scan100 unchanged from R5.
// ---------------------------------------------------------------------------

#define TLEN 1024
#define BSZ  128
#define HPAD 256

typedef unsigned long long u64;

__device__ float g_zx[(size_t)BSZ * TLEN * 800];  // x@Wx+b, layout [b][t][j][4]
__device__ float g_seq[(size_t)BSZ * TLEN * 200]; // layer output sequence
__device__ float g_hbuf[BSZ * HPAD];              // final h for dense head

#define FMA2(d, a, b, c) \
    asm("fma.rn.f32x2 %0, %1, %2, %3;" : "=l"(d) : "l"(a), "l"(b), "l"(c))

__device__ __forceinline__ u64 pack2(float lo, float hi) {
    u64 d;
    asm("mov.b64 %0, {%1, %2};" : "=l"(d)
        : "r"(__float_as_uint(lo)), "r"(__float_as_uint(hi)));
    return d;
}
__device__ __forceinline__ float2 unpack2(u64 v) {
    unsigned lo, hi;
    asm("mov.b64 {%0, %1}, %2;" : "=r"(lo), "=r"(hi) : "l"(v));
    return make_float2(__uint_as_float(lo), __uint_as_float(hi));
}

__device__ __forceinline__ float sigm(float x) {
    return __fdividef(1.0f, 1.0f + __expf(-x));
}
__device__ __forceinline__ float tanh_fast(float x) {
    return 1.0f - __fdividef(2.0f, __expf(2.0f * x) + 1.0f);
}

// Parity wait with cluster-scope acquire (remote DSMEM stores must be visible).
__device__ __forceinline__ void mbar_wait_parity_cluster(uint32_t bar, uint32_t parity) {
    uint32_t done;
    asm volatile(
        "{\n\t.reg .pred p;\n\t"
        "mbarrier.try_wait.parity.acquire.cluster.shared::cta.b64 p, [%1], %2;\n\t"
        "selp.b32 %0, 1, 0, p;\n\t}"
        : "=r"(done) : "r"(bar), "r"(parity) : "memory");
    if (!done) {
        asm volatile(
            "{\n\t.reg .pred P1;\n\t"
            "WAIT_LOOP_%=:\n\t"
            "mbarrier.try_wait.parity.acquire.cluster.shared::cta.b64 P1, [%0], %1, 0x989680;\n\t"
            "@P1 bra.uni WAIT_DONE_%=;\n\t"
            "bra.uni WAIT_LOOP_%=;\n\t"
            "WAIT_DONE_%=:\n\t}"
            :: "r"(bar), "r"(parity) : "memory");
    }
}

// ---------------------------------------------------------------------------
// Precompute GEMM (R5 version): C[M, n] = A[M,K] @ W[K, colmap(n)] + bias.
// colmap(n) = (n&3)*Hn + (n>>2)  (gate-interleaved zx layout for the scans).
// 128x128 CTA tile, 256 threads, 8x8 thread tile (m-paired f32x2 FFMA),
// KC=8 double-buffered smem with register prefetch.
// ---------------------------------------------------------------------------
template <int K>
__global__ void __launch_bounds__(256, 2)
gemm_x(const float* __restrict__ Ain, const float* __restrict__ W,
       const float* __restrict__ bias, int N, int Hn, int use_seq)
{
    constexpr int KC = 8;
    constexpr int NCHUNK = (K + KC - 1) / KC;

    __shared__ __align__(16) float A_s[2][KC][132];
    __shared__ __align__(16) float W_s[2][KC][132];

    const float* __restrict__ A = use_seq ? g_seq : Ain;
    const int tid = threadIdx.x;
    const int tx = tid & 15, ty = tid >> 4;
    const int m0 = blockIdx.y * 128, n0 = blockIdx.x * 128;

    const int a_row = tid >> 3, a_kk = tid & 7;
    const int w_kk0 = tid >> 7, w_n = tid & 127;
    const int wcol  = n0 + w_n;
    const int wsrc  = (wcol & 3) * Hn + (wcol >> 2);

    float aR[4], wR[4];

    auto ldA = [&](int c) {
        const int k0 = c * KC;
        #pragma unroll
        for (int e = 0; e < 4; ++e) {
            int row = a_row + 32 * e;
            aR[e] = (k0 + a_kk < K) ? A[(size_t)(m0 + row) * K + k0 + a_kk] : 0.0f;
        }
    };
    auto ldW = [&](int c) {
        const int k0 = c * KC;
        #pragma unroll
        for (int e = 0; e < 4; ++e) {
            int kk = 2 * e + w_kk0;
            float v = 0.0f;
            if ((k0 + kk < K) && (wcol < N)) v = W[(size_t)(k0 + kk) * N + wsrc];
            wR[e] = v;
        }
    };
    auto stA = [&](int buf) {
        #pragma unroll
        for (int e = 0; e < 4; ++e) A_s[buf][a_kk][a_row + 32 * e] = aR[e];
    };
    auto stW = [&](int buf) {
        #pragma unroll
        for (int e = 0; e < 4; ++e) W_s[buf][2 * e + w_kk0][w_n] = wR[e];
    };

    ldA(0); ldW(0);
    stA(0); stW(0);
    __syncthreads();

    u64 acc2[4][8];
    #pragma unroll
    for (int mp = 0; mp < 4; ++mp)
        #pragma unroll
        for (int j = 0; j < 8; ++j) acc2[mp][j] = 0ull;

    for (int c = 0; c < NCHUNK; ++c) {
        const int buf = c & 1;
        if (c + 1 < NCHUNK) { ldA(c + 1); ldW(c + 1); }
        #pragma unroll
        for (int k = 0; k < KC; ++k) {
            ulonglong2 ap0 = *reinterpret_cast<const ulonglong2*>(&A_s[buf][k][ty * 8]);
            ulonglong2 ap1 = *reinterpret_cast<const ulonglong2*>(&A_s[buf][k][ty * 8 + 4]);
            float4 w0 = *reinterpret_cast<const float4*>(&W_s[buf][k][tx * 8]);
            float4 w1 = *reinterpret_cast<const float4*>(&W_s[buf][k][tx * 8 + 4]);
            u64 ap[4] = {ap0.x, ap0.y, ap1.x, ap1.y};
            u64 wd[8];
            wd[0] = pack2(w0.x, w0.x); wd[1] = pack2(w0.y, w0.y);
            wd[2] = pack2(w0.z, w0.z); wd[3] = pack2(w0.w, w0.w);
            wd[4] = pack2(w1.x, w1.x); wd[5] = pack2(w1.y, w1.y);
            wd[6] = pack2(w1.z, w1.z); wd[7] = pack2(w1.w, w1.w);
            #pragma unroll
            for (int mp = 0; mp < 4; ++mp)
                #pragma unroll
                for (int j = 0; j < 8; ++j)
                    FMA2(acc2[mp][j], ap[mp], wd[j], acc2[mp][j]);
        }
        if (c + 1 < NCHUNK) { stA(buf ^ 1); stW(buf ^ 1); }
        __syncthreads();
    }

    float accf[8][8];
    #pragma unroll
    for (int mp = 0; mp < 4; ++mp)
        #pragma unroll
        for (int j = 0; j < 8; ++j) {
            float2 t = unpack2(acc2[mp][j]);
            accf[2 * mp][j]     = t.x;
            accf[2 * mp + 1][j] = t.y;
        }

    if (n0 + tx * 8 < N) {
        float b[8];
        #pragma unroll
        for (int j = 0; j < 8; ++j) {
            int cc = n0 + tx * 8 + j;
            b[j] = bias[(cc & 3) * Hn + (cc >> 2)];
        }
        #pragma unroll
        for (int i = 0; i < 8; ++i) {
            size_t off = (size_t)(m0 + ty * 8 + i) * N + (n0 + tx * 8);
            float4 v0 = make_float4(accf[i][0] + b[0], accf[i][1] + b[1],
                                    accf[i][2] + b[2], accf[i][3] + b[3]);
            float4 v1 = make_float4(accf[i][4] + b[4], accf[i][5] + b[5],
                                    accf[i][6] + b[6], accf[i][7] + b[7]);
            *reinterpret_cast<float4*>(&g_zx[off])     = v0;
            *reinterpret_cast<float4*>(&g_zx[off + 4]) = v1;
        }
    }
}

// ---------------------------------------------------------------------------
// H=100 scan (unchanged from R5): 1 CTA per batch row, Wh in regs (k-paired
// f32x2), h in SMEM, zx float4 with 2-deep register prefetch ring.
// ---------------------------------------------------------------------------
__global__ void __launch_bounds__(512, 1)
scan100(const float* __restrict__ Wh)
{
    __shared__ __align__(16) float  h_s[104];
    __shared__ __align__(16) float4 zp[5][100];

    const int tid = threadIdx.x;
    const int b   = blockIdx.x;
    const int s   = tid / 100;
    const int j   = tid % 100;
    const bool ga  = (tid < 500);
    const bool red = (tid < 100);

    u64 w2[10][4];
    if (ga) {
        const int k0 = s * 20;
        #pragma unroll
        for (int kp = 0; kp < 10; ++kp)
            #pragma unroll
            for (int g = 0; g < 4; ++g)
                w2[kp][g] = pack2(Wh[(k0 + 2 * kp)     * 400 + g * 100 + j],
                                  Wh[(k0 + 2 * kp + 1) * 400 + g * 100 + j]);
    }
    if (red) h_s[j] = 0.0f;
    float c = 0.0f;
    __syncthreads();

    const float* __restrict__ zbase = g_zx + (size_t)b * TLEN * 400;
    float* __restrict__ ybase = g_seq + (size_t)b * TLEN * 100;

    float4 zb0 = make_float4(0, 0, 0, 0), zb1 = zb0;
    if (red) {
        zb0 = *reinterpret_cast<const float4*>(zbase + j * 4);
        zb1 = *reinterpret_cast<const float4*>(zbase + 400 + j * 4);
    }

    auto step = [&](int t, float4& zslot) {
        float4 zc;
        if (red) {
            zc = zslot;
            int tp = (t + 2 < TLEN) ? t + 2 : t;
            zslot = *reinterpret_cast<const float4*>(zbase + (size_t)tp * 400 + j * 4);
        }
        if (ga) {
            u64 a0 = 0ull, a1 = 0ull, a2 = 0ull, a3 = 0ull;
            const ulonglong2* hp = reinterpret_cast<const ulonglong2*>(h_s);
            const int qb = s * 5;
            #pragma unroll
            for (int q = 0; q < 5; ++q) {
                ulonglong2 hv = hp[qb + q];
                FMA2(a0, hv.x, w2[2 * q][0], a0);
                FMA2(a1, hv.x, w2[2 * q][1], a1);
                FMA2(a2, hv.x, w2[2 * q][2], a2);
                FMA2(a3, hv.x, w2[2 * q][3], a3);
                FMA2(a0, hv.y, w2[2 * q + 1][0], a0);
                FMA2(a1, hv.y, w2[2 * q + 1][1], a1);
                FMA2(a2, hv.y, w2[2 * q + 1][2], a2);
                FMA2(a3, hv.y, w2[2 * q + 1][3], a3);
            }
            float2 p0 = unpack2(a0), p1 = unpack2(a1), p2 = unpack2(a2), p3 = unpack2(a3);
            zp[s][j] = make_float4(p0.x + p0.y, p1.x + p1.y, p2.x + p2.y, p3.x + p3.y);
        }
        __syncthreads();
        if (red) {
            float z0 = zc.x, z1 = zc.y, z2 = zc.z, z3 = zc.w;
            #pragma unroll
            for (int ss = 0; ss < 5; ++ss) {
                float4 p = zp[ss][j];
                z0 += p.x; z1 += p.y; z2 += p.z; z3 += p.w;
            }
            float gi = sigm(z0), gf = sigm(z1), gg = tanh_fast(z2), go = sigm(z3);
            c = gf * c + gi * gg;
            float h = go * tanh_fast(c);
            h_s[j] = h;
            ybase[(size_t)t * 100 + j] = h;
        }
        __syncthreads();
    };

    for (int t = 0; t < TLEN; t += 2) {
        step(t,     zb0);
        step(t + 1, zb1);
    }
}

// ---------------------------------------------------------------------------
// H=200 scan: cluster of 4 CTAs; rank owns j-slice [50r, 50r+50); cluster owns
// 4 batch rows. Wh slice in regs (k-paired f32x2); h double-buffered in SMEM.
// R7: per-step sync = st.async (tx-counted DSMEM stores) + mbarrier parity
// wait, replacing barrier.cluster (~490 cyc -> ~90 cyc).
// ---------------------------------------------------------------------------
template <int WRITE_Y>
__global__ void __launch_bounds__(512, 1) __cluster_dims__(4, 1, 1)
scan200(const float* __restrict__ Wh)
{
    __shared__ __align__(16) float  h_s[2][4][208];   // [buf][row][k]
    __shared__ __align__(16) float4 zp[10][4][50];    // [split][row][jl]
    __shared__ __align__(8)  u64    hbar;             // tx-counted mbarrier

    const int tid = threadIdx.x;
    uint32_t rank;
    asm("mov.u32 %0, %%cluster_ctarank;" : "=r"(rank));
    const int cl = blockIdx.x >> 2;

    const int s  = tid / 50;               // gemm split 0..9 (tid<500)
    const int jl = tid % 50;
    const bool ga  = (tid < 500);
    const bool red = (tid < 200);          // reduce row = s (0..3)
    const int  rr  = s;
    const int  jg  = (int)rank * 50 + jl;

    uint32_t hs_addr, bar_addr;
    {
        const void* p = (const void*)&h_s[0][0][0];
        asm("{ .reg .u64 t; cvta.to.shared.u64 t, %1; cvt.u32.u64 %0, t; }"
            : "=r"(hs_addr) : "l"(p));
        const void* q = (const void*)&hbar;
        asm("{ .reg .u64 t; cvta.to.shared.u64 t, %1; cvt.u32.u64 %0, t; }"
            : "=r"(bar_addr) : "l"(q));
    }

    // k-paired weights: w2[kp][g] = {W[k][g][jg], W[k+1][g][jg]}
    u64 w2[10][4];
    if (ga) {
        const int k0 = s * 20;
        #pragma unroll
        for (int kp = 0; kp < 10; ++kp)
            #pragma unroll
            for (int g = 0; g < 4; ++g)
                w2[kp][g] = pack2(Wh[(k0 + 2 * kp)     * 800 + g * 200 + jg],
                                  Wh[(k0 + 2 * kp + 1) * 800 + g * 200 + jg]);
    }
    for (int i = tid; i < 2 * 4 * 208; i += 512) (&h_s[0][0][0])[i] = 0.0f;
    if (tid == 0) {
        asm volatile("mbarrier.init.shared.b64 [%0], %1;"
                     :: "r"(bar_addr), "r"(1u) : "memory");
    }
    float c = 0.0f;
    __syncthreads();
    // barriers + zeroed h visible cluster-wide before any st.async
    asm volatile("barrier.cluster.arrive.aligned;" ::: "memory");
    asm volatile("barrier.cluster.wait.aligned;" ::: "memory");

    const int b = cl * 4 + rr;
    const float* __restrict__ zbase = g_zx + (size_t)b * TLEN * 800;
    float* __restrict__ ybase = g_seq + (size_t)b * TLEN * 200;

    float4 zb0 = make_float4(0, 0, 0, 0), zb1 = zb0;
    if (red) {
        zb0 = *reinterpret_cast<const float4*>(zbase + jg * 4);
        zb1 = *reinterpret_cast<const float4*>(zbase + 800 + jg * 4);
    }

    // per-step received bytes: 4 source CTAs x 200 floats = 3200 B
    constexpr uint32_t TX_BYTES = 4u * 200u * 4u;

    auto step = [&](int t, float4& zslot, int cur) {
        if (tid == 0) {
            asm volatile("mbarrier.arrive.expect_tx.shared.b64 _, [%0], %1;"
                         :: "r"(bar_addr), "r"(TX_BYTES) : "memory");
        }
        float4 zc;
        if (red) {
            zc = zslot;
            int tp = (t + 2 < TLEN) ? t + 2 : t;
            zslot = *reinterpret_cast<const float4*>(zbase + (size_t)tp * 800 + jg * 4);
        }
        if (ga) {
            const int qb = s * 5;
            #pragma unroll
            for (int r2 = 0; r2 < 4; ++r2) {   // one row at a time (reg-lean)
                u64 a0 = 0ull, a1 = 0ull, a2 = 0ull, a3 = 0ull;
                const ulonglong2* hp =
                    reinterpret_cast<const ulonglong2*>(&h_s[cur][r2][0]);
                #pragma unroll
                for (int q = 0; q < 5; ++q) {
                    ulonglong2 hv = hp[qb + q];
                    FMA2(a0, hv.x, w2[2 * q][0], a0);
                    FMA2(a1, hv.x, w2[2 * q][1], a1);
                    FMA2(a2, hv.x, w2[2 * q][2], a2);
                    FMA2(a3, hv.x, w2[2 * q][3], a3);
                    FMA2(a0, hv.y, w2[2 * q + 1][0], a0);
                    FMA2(a1, hv.y, w2[2 * q + 1][1], a1);
                    FMA2(a2, hv.y, w2[2 * q + 1][2], a2);
                    FMA2(a3, hv.y, w2[2 * q + 1][3], a3);
                }
                float2 p0 = unpack2(a0), p1 = unpack2(a1),
                       p2 = unpack2(a2), p3 = unpack2(a3);
                zp[s][r2][jl] = make_float4(p0.x + p0.y, p1.x + p1.y,
                                            p2.x + p2.y, p3.x + p3.y);
            }
        }
        __syncthreads();
        if (red) {
            float z0 = zc.x, z1 = zc.y, z2 = zc.z, z3 = zc.w;
            #pragma unroll
            for (int ss = 0; ss < 10; ++ss) {
                float4 p = zp[ss][rr][jl];
                z0 += p.x; z1 += p.y; z2 += p.z; z3 += p.w;
            }
            float gi = sigm(z0), gf = sigm(z1), gg = tanh_fast(z2), go = sigm(z3);
            c = gf * c + gi * gg;
            float h = go * tanh_fast(c);

            const int nxt = cur ^ 1;
            uint32_t laddr = hs_addr + (uint32_t)((nxt * 4 + rr) * 208 + jg) * 4u;
            #pragma unroll
            for (int p = 0; p < 4; ++p) {
                uint32_t rdata, rbar;
                asm("mapa.shared::cluster.u32 %0, %1, %2;"
                    : "=r"(rdata) : "r"(laddr), "r"(p));
                asm("mapa.shared::cluster.u32 %0, %1, %2;"
                    : "=r"(rbar) : "r"(bar_addr), "r"(p));
                asm volatile(
                    "st.async.shared::cluster.mbarrier::complete_tx::bytes.f32 "
                    "[%0], %1, [%2];"
                    :: "r"(rdata), "f"(h), "r"(rbar) : "memory");
            }
            if (WRITE_Y) ybase[(size_t)t * 200 + jg] = h;
            if (t == TLEN - 1) g_hbuf[b * HPAD + jg] = h;
        }
        mbar_wait_parity_cluster(bar_addr, (uint32_t)(t & 1));
    };

    for (int t = 0; t < TLEN; t += 2) {
        step(t,     zb0, 0);
        step(t + 1, zb1, 1);
    }

    // keep cluster resident until everyone's final waits are done
    asm volatile("barrier.cluster.arrive.aligned;" ::: "memory");
    asm volatile("barrier.cluster.wait.aligned;" ::: "memory");
}

// Final dense: out[b, o] = h_last[b, :200] @ Wd + bd.
__global__ void dense_kernel(const float* __restrict__ Wd,
                             const float* __restrict__ bd,
                             float* __restrict__ out)
{
    int idx = blockIdx.x * blockDim.x + threadIdx.x;
    if (idx >= BSZ * 6) return;
    int b = idx / 6, o = idx - b * 6;
    const float* h = g_hbuf + b * HPAD;
    float s = bd[o];
    #pragma unroll 8
    for (int k = 0; k < 200; ++k) s += h[k] * Wd[k * 6 + o];
    out[idx] = s;
}

extern "C" void kernel_launch(void* const* d_in, const int* in_sizes, int n_in,
                              void* d_out, int out_size)
{
    const float* xs  = (const float*)d_in[0];
    const float* Wx0 = (const float*)d_in[1];
    const float* Wh0 = (const float*)d_in[2];
    const float* b0  = (const float*)d_in[3];
    const float* Wx1 = (const float*)d_in[4];
    const float* Wh1 = (const float*)d_in[5];
    const float* b1  = (const float*)d_in[6];
    const float* Wx2 = (const float*)d_in[7];
    const float* Wh2 = (const float*)d_in[8];
    const float* b2  = (const float*)d_in[9];
    const float* Wx3 = (const float*)d_in[10];
    const float* Wh3 = (const float*)d_in[11];
    const float* b3  = (const float*)d_in[12];
    const float* Wd  = (const float*)d_in[13];
    const float* bd  = (const float*)d_in[14];

    const dim3 gN400(4, 1024);   // ceil(400/128) x (131072/128)
    const dim3 gN800(7, 1024);   // ceil(800/128)

    // L0
    gemm_x<128><<<gN400, 256>>>(xs, Wx0, b0, 400, 100, 0);
    scan100<<<BSZ, 512>>>(Wh0);
    // L1
    gemm_x<100><<<gN400, 256>>>(nullptr, Wx1, b1, 400, 100, 1);
    scan100<<<BSZ, 512>>>(Wh1);
    // L2
    gemm_x<100><<<gN800, 256>>>(nullptr, Wx2, b2, 800, 200, 1);
    scan200<1><<<BSZ, 512>>>(Wh2);
    // L3
    gemm_x<200><<<gN800, 256>>>(nullptr, Wx3, b3, 800, 200, 1);
    scan200<0><<<BSZ, 512>>>(Wh3);
    // head
    dense_kernel<<<3, 256>>>(Wd, bd, (float*)d_out);
}